// round 7
// baseline (speedup 1.0000x reference)
#include <cuda_runtime.h>

// Rayleigh-Bénard RHS, float4 along z, occupancy-optimized (<=64 regs).
// One warp = one (i,j) z-column; z halos via warp shuffle.
// Early-consumption load ordering keeps transient register peak low so
// 4 CTAs/SM fit (32 warps, ~50% occ).

#define NXg 256
#define NYg 256
#define NZg 128

__device__ __forceinline__ float4 operator+(float4 a, float4 b){return make_float4(a.x+b.x,a.y+b.y,a.z+b.z,a.w+b.w);}
__device__ __forceinline__ float4 operator-(float4 a, float4 b){return make_float4(a.x-b.x,a.y-b.y,a.z-b.z,a.w-b.w);}
__device__ __forceinline__ float4 operator*(float4 a, float4 b){return make_float4(a.x*b.x,a.y*b.y,a.z*b.z,a.w*b.w);}
__device__ __forceinline__ float4 operator*(float a, float4 b){return make_float4(a*b.x,a*b.y,a*b.z,a*b.w);}

__device__ __forceinline__ float4 d1z4(float4 q, float prev, float next, int lane, float s) {
    float4 r;
    r.x = (lane == 0)  ? (-3.0f*q.x + 4.0f*q.y - q.z) * s : (q.y - prev) * s;
    r.y = (q.z - q.x) * s;
    r.z = (q.w - q.y) * s;
    r.w = (lane == 31) ? ( 3.0f*q.w - 4.0f*q.z + q.y) * s : (next - q.z) * s;
    return r;
}

__device__ __forceinline__ float4 d2z4(float4 q, float prev, float next, int lane, float s) {
    float4 r;
    r.x = (lane == 0)  ? (2.0f*q.x - 5.0f*q.y + 4.0f*q.z - q.w) * s : (prev - 2.0f*q.x + q.y) * s;
    r.y = (q.x - 2.0f*q.y + q.z) * s;
    r.z = (q.y - 2.0f*q.z + q.w) * s;
    r.w = (lane == 31) ? (2.0f*q.w - 5.0f*q.z + 4.0f*q.y - q.x) * s : (q.z - 2.0f*q.w + next) * s;
    return r;
}

__global__ __launch_bounds__(256, 4)
void rbm_rhs4_kernel(const float* __restrict__ st, float* __restrict__ out) {
    const int lane = threadIdx.x;                        // z chunk (4 pts)
    const int j = blockIdx.x * blockDim.y + threadIdx.y; // y
    const int i = blockIdx.y;                            // x

    constexpr int PL4 = NYg * NZg / 4;
    constexpr int NZ4 = NZg / 4;
    constexpr int FS4 = NXg * NYg * NZg / 4;

    constexpr float CP = 1004.0f, CVc = 717.0f, MU = 1.8e-5f, KTH = 0.025f, Gc = 9.8f;
    constexpr float Rg = CP - CVc;
    constexpr float INV2DX = 0.5f * NXg;
    constexpr float INV2DY = 0.5f * NYg;
    constexpr float INV2DZ = 0.5f * (NZg - 1);
    constexpr float INVDX2 = (float)NXg * NXg;
    constexpr float INVDY2 = (float)NYg * NYg;
    constexpr float INVDZ2 = (float)(NZg - 1) * (NZg - 1);

    const int c_i  = i * PL4 + j * NZ4 + lane;
    const int xp_i = ((i + 1) & (NXg - 1)) * PL4 + j * NZ4 + lane;
    const int xm_i = ((i - 1) & (NXg - 1)) * PL4 + j * NZ4 + lane;
    const int yp_i = i * PL4 + ((j + 1) & (NYg - 1)) * NZ4 + lane;
    const int ym_i = i * PL4 + ((j - 1) & (NYg - 1)) * NZ4 + lane;

    const float4* S = (const float4*)st;
    float4* O = (float4*)out;
    const unsigned FULL = 0xFFFFFFFFu;
    const bool wallLo = (lane == 0), wallHi = (lane == 31);

    // persistent centers
    const float4 u   = S[0*FS4 + c_i];
    const float4 v   = S[1*FS4 + c_i];
    const float4 w   = S[2*FS4 + c_i];
    const float4 rou = S[3*FS4 + c_i];
    const float4 T   = S[4*FS4 + c_i];
    const float4 inv_rou = make_float4(1.0f/rou.x, 1.0f/rou.y, 1.0f/rou.z, 1.0f/rou.w);

    // ---------------- u section: dpdx, drou, du --------------------------
    {
        float4 pxp, pxm, drou;
        const float4 uxp = S[0*FS4 + xp_i];
        const float4 uxm = S[0*FS4 + xm_i];
        {
            // plus-side transients die immediately after folding
            const float4 rxp = S[3*FS4 + xp_i];
            const float4 Txp = S[4*FS4 + xp_i];
            pxp = rxp * Txp;
            drou = rxp * uxp;
        }
        {
            const float4 rxm = S[3*FS4 + xm_i];
            const float4 Txm = S[4*FS4 + xm_i];
            pxm = rxm * Txm;
            drou = (-INV2DX) * (drou - rxm * uxm);
        }
        O[3*FS4 + c_i] = drou;
        const float4 dpdx = (Rg * INV2DX) * (pxp - pxm);

        const float4 uyp = S[0*FS4 + yp_i];
        const float4 uym = S[0*FS4 + ym_i];
        const float u_prev = __shfl_up_sync(FULL, u.w, 1);
        const float u_next = __shfl_down_sync(FULL, u.x, 1);

        const float4 lap = INVDX2 * (uxp + uxm - 2.0f*u) + INVDY2 * (uyp + uym - 2.0f*u)
                         + d2z4(u, u_prev, u_next, lane, INVDZ2);
        const float4 adv = u * (INV2DX * (uxp - uxm)) + v * (INV2DY * (uyp - uym))
                         + w * d1z4(u, u_prev, u_next, lane, INV2DZ);
        float4 du = (MU * lap - dpdx) * inv_rou - adv;
        if (wallLo) du.x = 0.0f;
        if (wallHi) du.w = 0.0f;
        O[0*FS4 + c_i] = du;
    }

    // ---------------- v section: dpdy, dv --------------------------------
    {
        float4 pyp, pym;
        {
            const float4 ryp = S[3*FS4 + yp_i];
            const float4 Typ = S[4*FS4 + yp_i];
            pyp = ryp * Typ;
        }
        {
            const float4 rym = S[3*FS4 + ym_i];
            const float4 Tym = S[4*FS4 + ym_i];
            pym = rym * Tym;
        }
        const float4 dpdy = (Rg * INV2DY) * (pyp - pym);

        const float4 vxp = S[1*FS4 + xp_i];
        const float4 vxm = S[1*FS4 + xm_i];
        const float4 vyp = S[1*FS4 + yp_i];
        const float4 vym = S[1*FS4 + ym_i];
        const float v_prev = __shfl_up_sync(FULL, v.w, 1);
        const float v_next = __shfl_down_sync(FULL, v.x, 1);

        const float4 lap = INVDX2 * (vxp + vxm - 2.0f*v) + INVDY2 * (vyp + vym - 2.0f*v)
                         + d2z4(v, v_prev, v_next, lane, INVDZ2);
        const float4 adv = u * (INV2DX * (vxp - vxm)) + v * (INV2DY * (vyp - vym))
                         + w * d1z4(v, v_prev, v_next, lane, INV2DZ);
        float4 dv = (MU * lap - dpdy) * inv_rou - adv;
        if (wallLo) dv.x = 0.0f;
        if (wallHi) dv.w = 0.0f;
        O[1*FS4 + c_i] = dv;
    }

    // ---------------- T section (x-neighbors are L1 reloads) -------------
    {
        const float4 Txp = S[4*FS4 + xp_i];
        const float4 Txm = S[4*FS4 + xm_i];
        const float4 Typ = S[4*FS4 + yp_i];
        const float4 Tym = S[4*FS4 + ym_i];
        const float T_prev = __shfl_up_sync(FULL, T.w, 1);
        const float T_next = __shfl_down_sync(FULL, T.x, 1);

        const float4 lap = INVDX2 * (Txp + Txm - 2.0f*T) + INVDY2 * (Typ + Tym - 2.0f*T)
                         + d2z4(T, T_prev, T_next, lane, INVDZ2);
        const float4 adv = u * (INV2DX * (Txp - Txm)) + v * (INV2DY * (Typ - Tym))
                         + w * d1z4(T, T_prev, T_next, lane, INV2DZ);
        float4 dT = (KTH / CVc) * (lap * inv_rou) - adv;
        if (wallLo) dT.x = 0.0f;
        if (wallHi) dT.w = 0.0f;
        O[4*FS4 + c_i] = dT;
    }

    // ---------------- w section (dpdz from centers) ----------------------
    {
        const float4 wxp = S[2*FS4 + xp_i];
        const float4 wxm = S[2*FS4 + xm_i];
        const float4 wyp = S[2*FS4 + yp_i];
        const float4 wym = S[2*FS4 + ym_i];
        const float w_prev = __shfl_up_sync(FULL, w.w, 1);
        const float w_next = __shfl_down_sync(FULL, w.x, 1);

        const float4 p = Rg * (rou * T);
        const float p_prev = __shfl_up_sync(FULL, p.w, 1);
        const float p_next = __shfl_down_sync(FULL, p.x, 1);
        const float4 dpdz = d1z4(p, p_prev, p_next, lane, INV2DZ);

        const float4 lap = INVDX2 * (wxp + wxm - 2.0f*w) + INVDY2 * (wyp + wym - 2.0f*w)
                         + d2z4(w, w_prev, w_next, lane, INVDZ2);
        const float4 adv = u * (INV2DX * (wxp - wxm)) + v * (INV2DY * (wyp - wym))
                         + w * d1z4(w, w_prev, w_next, lane, INV2DZ);
        float4 dw = (MU * lap - dpdz - Gc * rou) * inv_rou - adv;
        if (wallLo) dw.x = 0.0f;
        if (wallHi) dw.w = 0.0f;
        O[2*FS4 + c_i] = dw;
    }

    // ---------------- c section ------------------------------------------
    {
        const float4 cc  = S[5*FS4 + c_i];
        const float4 cxp = S[5*FS4 + xp_i];
        const float4 cxm = S[5*FS4 + xm_i];
        const float4 cyp = S[5*FS4 + yp_i];
        const float4 cym = S[5*FS4 + ym_i];
        const float c_prev = __shfl_up_sync(FULL, cc.w, 1);
        const float c_next = __shfl_down_sync(FULL, cc.x, 1);

        const float4 adv = u * (INV2DX * (cxp - cxm)) + v * (INV2DY * (cyp - cym))
                         + w * d1z4(cc, c_prev, c_next, lane, INV2DZ);
        O[5*FS4 + c_i] = make_float4(-adv.x, -adv.y, -adv.z, -adv.w);
    }
}

extern "C" void kernel_launch(void* const* d_in, const int* in_sizes, int n_in,
                              void* d_out, int out_size) {
    const float* state = (const float*)d_in[0];
    float* out = (float*)d_out;
    dim3 block(32, 8);
    dim3 grid(NYg / 8, NXg);
    rbm_rhs4_kernel<<<grid, block>>>(state, out);
}

// round 9
// speedup vs baseline: 1.0998x; 1.0998x over previous
#include <cuda_runtime.h>

// Rayleigh-Bénard RHS, float4 along z (R5 structure, 82.4us baseline).
// R8: __ldcs (evict-first) for x-neighbor loads (no intra-block reuse),
// x-loads issued first per section, launch_bounds(256,3) = 85-reg frontier.

#define NXg 256
#define NYg 256
#define NZg 128

__device__ __forceinline__ float4 operator+(float4 a, float4 b){return make_float4(a.x+b.x,a.y+b.y,a.z+b.z,a.w+b.w);}
__device__ __forceinline__ float4 operator-(float4 a, float4 b){return make_float4(a.x-b.x,a.y-b.y,a.z-b.z,a.w-b.w);}
__device__ __forceinline__ float4 operator*(float4 a, float4 b){return make_float4(a.x*b.x,a.y*b.y,a.z*b.z,a.w*b.w);}
__device__ __forceinline__ float4 operator*(float a, float4 b){return make_float4(a*b.x,a*b.y,a*b.z,a*b.w);}

__device__ __forceinline__ float4 d1z4(float4 q, float prev, float next, int lane, float s) {
    float4 r;
    r.x = (lane == 0)  ? (-3.0f*q.x + 4.0f*q.y - q.z) * s : (q.y - prev) * s;
    r.y = (q.z - q.x) * s;
    r.z = (q.w - q.y) * s;
    r.w = (lane == 31) ? ( 3.0f*q.w - 4.0f*q.z + q.y) * s : (next - q.z) * s;
    return r;
}

__device__ __forceinline__ float4 d2z4(float4 q, float prev, float next, int lane, float s) {
    float4 r;
    r.x = (lane == 0)  ? (2.0f*q.x - 5.0f*q.y + 4.0f*q.z - q.w) * s : (prev - 2.0f*q.x + q.y) * s;
    r.y = (q.x - 2.0f*q.y + q.z) * s;
    r.z = (q.y - 2.0f*q.z + q.w) * s;
    r.w = (lane == 31) ? (2.0f*q.w - 5.0f*q.z + 4.0f*q.y - q.x) * s : (q.z - 2.0f*q.w + next) * s;
    return r;
}

__global__ __launch_bounds__(256, 3)
void rbm_rhs4_kernel(const float* __restrict__ st, float* __restrict__ out) {
    const int lane = threadIdx.x;                        // z chunk (4 pts)
    const int j = blockIdx.x * blockDim.y + threadIdx.y; // y
    const int i = blockIdx.y;                            // x

    constexpr int PL4 = NYg * NZg / 4;
    constexpr int NZ4 = NZg / 4;
    constexpr int FS4 = NXg * NYg * NZg / 4;

    constexpr float CP = 1004.0f, CVc = 717.0f, MU = 1.8e-5f, KTH = 0.025f, Gc = 9.8f;
    constexpr float Rg = CP - CVc;
    constexpr float INV2DX = 0.5f * NXg;
    constexpr float INV2DY = 0.5f * NYg;
    constexpr float INV2DZ = 0.5f * (NZg - 1);
    constexpr float INVDX2 = (float)NXg * NXg;
    constexpr float INVDY2 = (float)NYg * NYg;
    constexpr float INVDZ2 = (float)(NZg - 1) * (NZg - 1);

    const int c_i  = i * PL4 + j * NZ4 + lane;
    const int xp_i = ((i + 1) & (NXg - 1)) * PL4 + j * NZ4 + lane;
    const int xm_i = ((i - 1) & (NXg - 1)) * PL4 + j * NZ4 + lane;
    const int yp_i = i * PL4 + ((j + 1) & (NYg - 1)) * NZ4 + lane;
    const int ym_i = i * PL4 + ((j - 1) & (NYg - 1)) * NZ4 + lane;

    const float4* S = (const float4*)st;
    float4* O = (float4*)out;
    const unsigned FULL = 0xFFFFFFFFu;
    const bool wallLo = (lane == 0), wallHi = (lane == 31);

    // persistent centers (reused by adjacent warps via L1 -> default policy)
    const float4 u   = S[0*FS4 + c_i];
    const float4 v   = S[1*FS4 + c_i];
    const float4 w   = S[2*FS4 + c_i];
    const float4 rou = S[3*FS4 + c_i];
    const float4 T   = S[4*FS4 + c_i];
    const float4 inv_rou = make_float4(1.0f/rou.x, 1.0f/rou.y, 1.0f/rou.z, 1.0f/rou.w);

    // ---------------- u section (+ dpdx, drou) ----------------
    {
        // x-neighbors: streaming (no intra-block reuse), issue first
        const float4 uxp = __ldcs(&S[0*FS4 + xp_i]);
        const float4 uxm = __ldcs(&S[0*FS4 + xm_i]);
        const float4 rxp = __ldcs(&S[3*FS4 + xp_i]);
        const float4 rxm = __ldcs(&S[3*FS4 + xm_i]);
        const float4 Txp = __ldcs(&S[4*FS4 + xp_i]);
        const float4 Txm = __ldcs(&S[4*FS4 + xm_i]);
        const float4 uyp = S[0*FS4 + yp_i];
        const float4 uym = S[0*FS4 + ym_i];
        const float u_prev = __shfl_up_sync(FULL, u.w, 1);
        const float u_next = __shfl_down_sync(FULL, u.x, 1);

        const float4 dpdx = (Rg * INV2DX) * (rxp * Txp - rxm * Txm);
        const float4 lap = INVDX2 * (uxp + uxm - 2.0f*u) + INVDY2 * (uyp + uym - 2.0f*u)
                         + d2z4(u, u_prev, u_next, lane, INVDZ2);
        const float4 adv = u * (INV2DX * (uxp - uxm)) + v * (INV2DY * (uyp - uym))
                         + w * d1z4(u, u_prev, u_next, lane, INV2DZ);
        float4 du = (MU * lap - dpdx) * inv_rou - adv;
        if (wallLo) du.x = 0.0f;
        if (wallHi) du.w = 0.0f;
        O[0*FS4 + c_i] = du;

        float4 drou = (-INV2DX) * (rxp * uxp - rxm * uxm);
        O[3*FS4 + c_i] = drou;
    }

    // ---------------- v section (+ dpdy) ----------------
    {
        const float4 vxp = __ldcs(&S[1*FS4 + xp_i]);
        const float4 vxm = __ldcs(&S[1*FS4 + xm_i]);
        const float4 vyp = S[1*FS4 + yp_i];
        const float4 vym = S[1*FS4 + ym_i];
        const float4 ryp = S[3*FS4 + yp_i];
        const float4 rym = S[3*FS4 + ym_i];
        const float4 Typ = S[4*FS4 + yp_i];
        const float4 Tym = S[4*FS4 + ym_i];
        const float v_prev = __shfl_up_sync(FULL, v.w, 1);
        const float v_next = __shfl_down_sync(FULL, v.x, 1);

        const float4 dpdy = (Rg * INV2DY) * (ryp * Typ - rym * Tym);
        const float4 lap = INVDX2 * (vxp + vxm - 2.0f*v) + INVDY2 * (vyp + vym - 2.0f*v)
                         + d2z4(v, v_prev, v_next, lane, INVDZ2);
        const float4 adv = u * (INV2DX * (vxp - vxm)) + v * (INV2DY * (vyp - vym))
                         + w * d1z4(v, v_prev, v_next, lane, INV2DZ);
        float4 dv = (MU * lap - dpdy) * inv_rou - adv;
        if (wallLo) dv.x = 0.0f;
        if (wallHi) dv.w = 0.0f;
        O[1*FS4 + c_i] = dv;
    }

    // ---------------- T section (x reloads: L2 hit; y reloads: L1 hit) ---
    {
        const float4 Txp = __ldcs(&S[4*FS4 + xp_i]);
        const float4 Txm = __ldcs(&S[4*FS4 + xm_i]);
        const float4 Typ = S[4*FS4 + yp_i];
        const float4 Tym = S[4*FS4 + ym_i];
        const float T_prev = __shfl_up_sync(FULL, T.w, 1);
        const float T_next = __shfl_down_sync(FULL, T.x, 1);

        const float4 lap = INVDX2 * (Txp + Txm - 2.0f*T) + INVDY2 * (Typ + Tym - 2.0f*T)
                         + d2z4(T, T_prev, T_next, lane, INVDZ2);
        const float4 adv = u * (INV2DX * (Txp - Txm)) + v * (INV2DY * (Typ - Tym))
                         + w * d1z4(T, T_prev, T_next, lane, INV2DZ);
        float4 dT = (KTH / CVc) * (lap * inv_rou) - adv;
        if (wallLo) dT.x = 0.0f;
        if (wallHi) dT.w = 0.0f;
        O[4*FS4 + c_i] = dT;
    }

    // ---------------- w section (dpdz from centers) ----------------------
    {
        const float4 wxp = __ldcs(&S[2*FS4 + xp_i]);
        const float4 wxm = __ldcs(&S[2*FS4 + xm_i]);
        const float4 wyp = S[2*FS4 + yp_i];
        const float4 wym = S[2*FS4 + ym_i];
        const float w_prev = __shfl_up_sync(FULL, w.w, 1);
        const float w_next = __shfl_down_sync(FULL, w.x, 1);

        const float4 p = Rg * (rou * T);
        const float p_prev = __shfl_up_sync(FULL, p.w, 1);
        const float p_next = __shfl_down_sync(FULL, p.x, 1);
        const float4 dpdz = d1z4(p, p_prev, p_next, lane, INV2DZ);

        const float4 lap = INVDX2 * (wxp + wxm - 2.0f*w) + INVDY2 * (wyp + wym - 2.0f*w)
                         + d2z4(w, w_prev, w_next, lane, INVDZ2);
        const float4 adv = u * (INV2DX * (wxp - wxm)) + v * (INV2DY * (wyp - wym))
                         + w * d1z4(w, w_prev, w_next, lane, INV2DZ);
        float4 dw = (MU * lap - dpdz - Gc * rou) * inv_rou - adv;
        if (wallLo) dw.x = 0.0f;
        if (wallHi) dw.w = 0.0f;
        O[2*FS4 + c_i] = dw;
    }

    // ---------------- c section ------------------------------------------
    {
        const float4 cxp = __ldcs(&S[5*FS4 + xp_i]);
        const float4 cxm = __ldcs(&S[5*FS4 + xm_i]);
        const float4 cc  = S[5*FS4 + c_i];
        const float4 cyp = S[5*FS4 + yp_i];
        const float4 cym = S[5*FS4 + ym_i];
        const float c_prev = __shfl_up_sync(FULL, cc.w, 1);
        const float c_next = __shfl_down_sync(FULL, cc.x, 1);

        const float4 adv = u * (INV2DX * (cxp - cxm)) + v * (INV2DY * (cyp - cym))
                         + w * d1z4(cc, c_prev, c_next, lane, INV2DZ);
        O[5*FS4 + c_i] = make_float4(-adv.x, -adv.y, -adv.z, -adv.w);
    }
}

extern "C" void kernel_launch(void* const* d_in, const int* in_sizes, int n_in,
                              void* d_out, int out_size) {
    const float* state = (const float*)d_in[0];
    float* out = (float*)d_out;
    dim3 block(32, 8);
    dim3 grid(NYg / 8, NXg);
    rbm_rhs4_kernel<<<grid, block>>>(state, out);
}